// round 16
// baseline (speedup 1.0000x reference)
#include <cuda_runtime.h>

// Depthwise conv_transpose2d(stride=4, k=7, bilinear) == separable x4 upsample.
// Input  x: [4, 256, 64, 64] fp32, Output: [4, 256, 259, 259] fp32.
//
// out[o] = wA*in[cell-1] + (1-wA)*in[cell], wA = 0.75-0.25*(o&3), OOB taps = 0.
//
// Row alignment phase hds(4a+py) = (py - plane) & 3 is constant per
// (plane, py): each output row = hds head scalars + 64 aligned float4
// chunks + (3-hds) tail scalars, decided at compile time via the plane&3
// template. Every chunk store is an aligned STG.128.
//
// Converged design (R14/R15 family, ~6.1 TB/s sustained = DRAM-write
// roofline): 13 slices x 5 y-blocks per plane, 64-thread blocks, ~3 waves;
// shuffle-based neighbor exchange (1 coalesced LDG/warp-row + boundary-lane
// scalar); 2-deep raw-row pipeline keeps LDG latency hidden.
// R16 delta: __launch_bounds__(64, 32) -> full 64-warp residency per SM.

namespace {
constexpr int H = 64, W = 64;
constexpr int OH = 259, OW = 259;
constexpr int PLANES = 4 * 256;   // 1024
constexpr int SLICE = 5;          // y-blocks per block
constexpr int NSLICES = 13;       // 13 * 5 = 65
}

template <int PM>   // plane & 3
__device__ __forceinline__ void run_group(
    const float* __restrict__ xp, float* __restrict__ op,
    int j, int b0, int b1)
{
    const int lane = j & 31;
    const int jn = j + ((lane == 0) ? -1 : 1);        // neighbor this lane fetches
    const bool eOk = ((lane == 0) || (lane == 31)) && ((unsigned)jn < (unsigned)W);

    // raw row load: center value + boundary-lane neighbor (both pipelined)
    auto loadRaw = [&](int r, float& c, float& e) {
        c = 0.f; e = 0.f;
        if ((unsigned)r < (unsigned)H) {
            const float* row = xp + r * W;
            c = __ldg(row + j);                       // coalesced, 128B-aligned
            if (eOk) e = __ldg(row + jn);             // lanes 0/31 only
        }
    };

    // reconstruct (t0,t1,t2) = row[j-1], row[j], row[j+1] via warp shuffles
    auto expand = [&](float c, float e, float& t0, float& t1, float& t2) {
        t1 = c;
        t0 = __shfl_up_sync(0xffffffffu, c, 1);
        if (lane == 0) t0 = (j == 0) ? 0.f : e;       // cross-warp / left edge
        t2 = __shfl_down_sync(0xffffffffu, c, 1);
        if (lane == 31) t2 = (j == 63) ? 0.f : e;     // cross-warp / right edge
    };

    auto doRow = [&](float* rowOut, float wy, int hds,
                     float dA0, float dA1, float dA2,
                     float B0, float B1, float B2) {
        float v0 = fmaf(wy, dA0, B0);
        float v1 = fmaf(wy, dA1, B1);
        float v2 = fmaf(wy, dA2, B2);
        float d0 = v0 - v1, d1 = v1 - v2;
        float4 o;
        if (hds == 0)
            o = make_float4(fmaf(0.75f,d0,v1), fmaf(0.50f,d0,v1), fmaf(0.25f,d0,v1), v1);
        else if (hds == 1)
            o = make_float4(fmaf(0.50f,d0,v1), fmaf(0.25f,d0,v1), v1, fmaf(0.75f,d1,v2));
        else if (hds == 2)
            o = make_float4(fmaf(0.25f,d0,v1), v1, fmaf(0.75f,d1,v2), fmaf(0.50f,d1,v2));
        else
            o = make_float4(v1, fmaf(0.75f,d1,v2), fmaf(0.50f,d1,v2), fmaf(0.25f,d1,v2));
        *reinterpret_cast<float4*>(rowOut + hds + 4 * j) = o;

        if (j == 0) {            // head scalars ox = 0..hds-1
#pragma unroll
            for (int s = 0; s < 3; s++)
                if (s < hds) rowOut[s] = fmaf(0.75f - 0.25f * s, d0, v1);
        } else if (j == 63) {    // tail scalars ox = 256+u, u = hds..2
#pragma unroll
            for (int u = 0; u < 3; u++)
                if (u >= hds) rowOut[256 + u] = fmaf(0.75f - 0.25f * u, d1, v2);
        }
    };

    constexpr int h0 = (0 - PM) & 3, h1 = (1 - PM) & 3;
    constexpr int h2 = (2 - PM) & 3, h3 = (3 - PM) & 3;

    // preamble: expand rows b0-1, b0; keep rows b0+1, b0+2 raw in flight
    float cA, eA, cB, eB, cN, eN;
    loadRaw(b0 - 1, cA, eA);
    loadRaw(b0,     cB, eB);
    loadRaw(b0 + 1, cN, eN);

    float A0, A1, A2, B0, B1, B2;
    expand(cA, eA, A0, A1, A2);
    expand(cB, eB, B0, B1, B2);

    float* r0 = op + (size_t)(4 * b0) * OW;   // accumulated row pointer

#pragma unroll 1
    for (int a = b0; a < b1; a++) {
        float cP, eP;
        loadRaw(a + 2, cP, eP);               // consumed 2 iterations later

        float dA0 = A0 - B0, dA1 = A1 - B1, dA2 = A2 - B2;
        doRow(r0,          0.75f, h0, dA0, dA1, dA2, B0, B1, B2);
        doRow(r0 + OW,     0.50f, h1, dA0, dA1, dA2, B0, B1, B2);
        doRow(r0 + 2 * OW, 0.25f, h2, dA0, dA1, dA2, B0, B1, B2);
        if (a < 64)
            doRow(r0 + 3 * OW, 0.0f, h3, dA0, dA1, dA2, B0, B1, B2);

        // rotate: expanded B -> A, expand raw N -> B, raw P -> N
        A0 = B0; A1 = B1; A2 = B2;
        expand(cN, eN, B0, B1, B2);
        cN = cP; eN = eP;
        r0 += 4 * OW;
    }
}

__global__ void __launch_bounds__(64, 32)
bilinear_up4_final_kernel(const float* __restrict__ x, float* __restrict__ out) {
    int j = threadIdx.x;               // chunk / cell index 0..63
    int slice = blockIdx.x;            // 0..12
    int plane = blockIdx.y;

    const float* xp = x + plane * (H * W);
    float* op = out + (size_t)plane * ((size_t)OH * OW);

    int b0 = slice * SLICE;
    int b1 = b0 + SLICE;               // uniform 5 y-blocks per block

    switch (plane & 3) {
        case 0:  run_group<0>(xp, op, j, b0, b1); break;
        case 1:  run_group<1>(xp, op, j, b0, b1); break;
        case 2:  run_group<2>(xp, op, j, b0, b1); break;
        default: run_group<3>(xp, op, j, b0, b1); break;
    }
}

extern "C" void kernel_launch(void* const* d_in, const int* in_sizes, int n_in,
                              void* d_out, int out_size) {
    const float* x = (const float*)d_in[0];
    float* out = (float*)d_out;
    (void)in_sizes; (void)n_in; (void)out_size;

    dim3 grid(NSLICES, PLANES);        // 13312 blocks x 64 threads, ~3 waves
    bilinear_up4_final_kernel<<<grid, 64>>>(x, out);
}